// round 13
// baseline (speedup 1.0000x reference)
#include <cuda_runtime.h>
#include <cuda_fp16.h>
#include <cstdint>

// ---------------------------------------------------------------------------
// EnsembleHead fused. B=1024, N=512, D_IN=30, H=64, 4H=256.
// R12: R11 (single-pass tensor-pipe recurrence, fused input GEMM, one
// barrier/step) + chunked x staging: 16-plane SMEM x ring, LDGs issued 16
// steps ahead in groups of 8 -> DRAM latency fully off the critical path.
// ---------------------------------------------------------------------------

typedef unsigned long long ull;
typedef unsigned int uint32;

#define Bsz   1024
#define Nseq  512
#define DIN   30
#define RPB   8
#define NBLK  (Bsz / RPB)   // 128
#define KTOT  96            // 64 h + 32 x (30 used)
#define LDH   72            // h row stride in halfs (bank-skewed)
#define LDX   40            // x plane row stride in halfs (bank-skewed)

__device__ __half g_wcomb_h[256 * KTOT];  // [n][k]: k<64 Whh, 64..93 Wc, 94/95 = 0
__device__ float  g_bc[256];

// ---------------- helpers ----------------
__device__ __forceinline__ float ex2a(float x) {
    float r; asm("ex2.approx.f32 %0, %1;" : "=f"(r) : "f"(x)); return r;
}
__device__ __forceinline__ float rcpa(float x) {
    float r; asm("rcp.approx.f32 %0, %1;" : "=f"(r) : "f"(x)); return r;
}
__device__ __forceinline__ float sigm(float x) {
    return rcpa(1.0f + ex2a(-1.4426950408889634f * x));
}
__device__ __forceinline__ float tanh_(float x) {
    return fmaf(2.0f, rcpa(1.0f + ex2a(-2.8853900817779268f * x)), -1.0f);
}
__device__ __forceinline__ void mma16816(float* c, uint32 a0, uint32 a1,
                                         uint32 a2, uint32 a3,
                                         uint32 b0, uint32 b1) {
    asm volatile(
        "mma.sync.aligned.m16n8k16.row.col.f32.f16.f16.f32 "
        "{%0,%1,%2,%3}, {%4,%5,%6,%7}, {%8,%9}, {%0,%1,%2,%3};"
        : "+f"(c[0]), "+f"(c[1]), "+f"(c[2]), "+f"(c[3])
        : "r"(a0), "r"(a1), "r"(a2), "r"(a3), "r"(b0), "r"(b1));
}

// ---------------------------------------------------------------------------
// prep: combined fp16 weight [n][96] = [Whh | Wih@Wfc | 0] and bias.
// grid=256 (n), block=32.
// ---------------------------------------------------------------------------
__global__ void prep_kernel(const float* __restrict__ Wfc,
                            const float* __restrict__ bfc,
                            const float* __restrict__ Wih,
                            const float* __restrict__ Whh,
                            const float* __restrict__ bih,
                            const float* __restrict__ bhh)
{
    const int j = blockIdx.x;
    const int lane = threadIdx.x;

    const float w1 = Wih[j * 64 + lane];
    const float w2 = Wih[j * 64 + lane + 32];
    float acc[DIN];
#pragma unroll
    for (int d = 0; d < DIN; ++d)
        acc[d] = w1 * Wfc[lane * DIN + d] + w2 * Wfc[(lane + 32) * DIN + d];
    float bs = w1 * bfc[lane] + w2 * bfc[lane + 32];

#pragma unroll
    for (int off = 16; off >= 1; off >>= 1) {
#pragma unroll
        for (int d = 0; d < DIN; ++d)
            acc[d] += __shfl_xor_sync(0xffffffffu, acc[d], off);
        bs += __shfl_xor_sync(0xffffffffu, bs, off);
    }

    g_wcomb_h[j * KTOT + 2 * lane]     = __float2half(Whh[j * 64 + 2 * lane]);
    g_wcomb_h[j * KTOT + 2 * lane + 1] = __float2half(Whh[j * 64 + 2 * lane + 1]);

    float a0 = 0.0f, a1 = 0.0f;
#pragma unroll
    for (int d = 0; d < DIN; ++d) {
        if (d == 2 * lane)     a0 = acc[d];
        if (d == 2 * lane + 1) a1 = acc[d];
    }
    if (lane < 16) {   // lane 15 writes zeros to cols 94,95
        g_wcomb_h[j * KTOT + 64 + 2 * lane]     = __float2half(a0);
        g_wcomb_h[j * KTOT + 64 + 2 * lane + 1] = __float2half(a1);
    }
    if (lane == 0) g_bc[j] = bs + bih[j] + bhh[j];
}

// ---------------------------------------------------------------------------
// lstm_kernel: 128 CTAs x 256 thr (8 warps), 1/SM.
// thread (wid, gid=lane>>2, tig=lane&3): row gid, units u0=wid*8+tig*2, u0+1.
// ---------------------------------------------------------------------------
__global__ void __launch_bounds__(256, 1)
lstm_kernel(const float* __restrict__ X,
            const float* __restrict__ Wlast,
            const float* __restrict__ blast,
            float* __restrict__ out)
{
    __shared__ __align__(16) __half sh[2][RPB][LDH];    // h double buffer
    __shared__ __align__(16) __half sx[16][RPB][LDX];   // x 16-plane ring
    __shared__ float s_wl[64];
    __shared__ float s_part[2][RPB][8];                 // [parity][row][warp]
    __shared__ float s_log[RPB * Nseq];

    const int tid  = threadIdx.x;
    const int lane = tid & 31;
    const int wid  = tid >> 5;
    const int b0   = blockIdx.x * RPB;
    const int gid  = lane >> 2;
    const int tig  = lane & 3;

    // zero h buffers and x ring (incl. pad cols), load Wlast
    for (int i = tid; i < (int)(2 * RPB * LDH / 2); i += 256) ((uint32*)sh)[i] = 0;
    for (int i = tid; i < (int)(16 * RPB * LDX / 2); i += 256) ((uint32*)sx)[i] = 0;
    if (tid < 64) s_wl[tid] = Wlast[tid];
    const float blv = blast[0];

    // B fragments: combined weight, n0 = gi*64 + wid*8 + gid
    uint32 bfr[4][6][2];
#pragma unroll
    for (int gi = 0; gi < 4; ++gi)
#pragma unroll
        for (int kt = 0; kt < 6; ++kt) {
            const int n0 = gi * 64 + wid * 8 + gid;
            const int k0 = kt * 16 + tig * 2;
            bfr[gi][kt][0] = *(const uint32*)(g_wcomb_h + n0 * KTOT + k0);
            bfr[gi][kt][1] = *(const uint32*)(g_wcomb_h + n0 * KTOT + k0 + 8);
        }
    float bia[4][2];
#pragma unroll
    for (int gi = 0; gi < 4; ++gi) {
        bia[gi][0] = g_bc[gi * 64 + wid * 8 + tig * 2];
        bia[gi][1] = g_bc[gi * 64 + wid * 8 + tig * 2 + 1];
    }

    // x staging role: tid<240 owns (row prow, dim pd)
    const bool px = tid < RPB * DIN;
    const int prow = tid / DIN;
    const int pd   = tid - prow * DIN;
    const float* xp = X + ((size_t)(b0 + prow) * Nseq) * DIN + pd;

    __syncthreads();   // zero-fill complete

    // prologue: steps 0..7 -> planes 0..7 (one-time LDG latency hit),
    // then load steps 8..15 into the register ring.
    float xr[8];
    if (px) {
        float v[8];
#pragma unroll
        for (int i = 0; i < 8; ++i) v[i] = xp[i * DIN];
#pragma unroll
        for (int i = 0; i < 8; ++i)
            sx[i][prow][pd] = __float2half(v[i]);
#pragma unroll
        for (int i = 0; i < 8; ++i) xr[i] = xp[(8 + i) * DIN];
    }
    __syncthreads();

    const float wl0 = s_wl[wid * 8 + tig * 2];
    const float wl1 = s_wl[wid * 8 + tig * 2 + 1];
    float cc0 = 0.0f, cc1 = 0.0f;

    for (int t = 0; t < Nseq; ++t) {
        const int buf = t & 1;
        const int tp  = t & 15;

        // chunk boundary: drain register ring into planes t+8..t+15 (loaded
        // 8 steps ago, scoreboard long drained), then LDG steps t+16..t+23.
        if ((t & 7) == 0 && px) {
            if (t + 8 < Nseq) {
#pragma unroll
                for (int i = 0; i < 8; ++i)
                    sx[(t + 8 + i) & 15][prow][pd] = __float2half(xr[i]);
            }
#pragma unroll
            for (int i = 0; i < 8; ++i)
                if (t + 16 + i < Nseq) xr[i] = xp[(t + 16 + i) * DIN];
        }

        // A fragments: kt 0..3 from h, kt 4..5 from x plane tp
        uint32 afr0[6], afr2[6];
#pragma unroll
        for (int kt = 0; kt < 4; ++kt) {
            const int cb = kt * 16 + tig * 2;
            afr0[kt] = *(const uint32*)&sh[buf][gid][cb];
            afr2[kt] = *(const uint32*)&sh[buf][gid][cb + 8];
        }
#pragma unroll
        for (int kt = 4; kt < 6; ++kt) {
            const int cb = (kt - 4) * 16 + tig * 2;
            afr0[kt] = *(const uint32*)&sx[tp][gid][cb];
            afr2[kt] = *(const uint32*)&sx[tp][gid][cb + 8];
        }

        // tensor matvec: [h,x] @ Wcomb^T, warp's 4 n-tiles (one per gate)
        float cfr[4][4];
#pragma unroll
        for (int gi = 0; gi < 4; ++gi) {
            cfr[gi][0] = 0.f; cfr[gi][1] = 0.f; cfr[gi][2] = 0.f; cfr[gi][3] = 0.f;
#pragma unroll
            for (int kt = 0; kt < 6; ++kt)
                mma16816(cfr[gi], afr0[kt], 0u, afr2[kt], 0u,
                         bfr[gi][kt][0], bfr[gi][kt][1]);
        }

        // local activation + cell update (all four gates in-register)
        float vi0 = cfr[0][0] + bia[0][0], vi1 = cfr[0][1] + bia[0][1];
        float vf0 = cfr[1][0] + bia[1][0], vf1 = cfr[1][1] + bia[1][1];
        float vg0 = cfr[2][0] + bia[2][0], vg1 = cfr[2][1] + bia[2][1];
        float vo0 = cfr[3][0] + bia[3][0], vo1 = cfr[3][1] + bia[3][1];

        float i0 = sigm(vi0), f0 = sigm(vf0), g0 = tanh_(vg0), o0 = sigm(vo0);
        float i1 = sigm(vi1), f1 = sigm(vf1), g1 = tanh_(vg1), o1 = sigm(vo1);
        cc0 = fmaf(f0, cc0, i0 * g0);
        cc1 = fmaf(f1, cc1, i1 * g1);
        float hv0 = o0 * tanh_(cc0);
        float hv1 = o1 * tanh_(cc1);

        // h(t+1) -> other buffer (units adjacent: one half2 store)
        *(__half2*)&sh[buf ^ 1][gid][wid * 8 + tig * 2] =
            __floats2half2_rn(hv0, hv1);

        // logit partial for row gid (this warp's 8 units), parity-buffered
        float p = hv0 * wl0 + hv1 * wl1;
        p += __shfl_down_sync(0xffffffffu, p, 1, 4);
        p += __shfl_down_sync(0xffffffffu, p, 2, 4);
        if (tig == 0) s_part[buf][gid][wid] = p;

        // combine previous step's logit partials (8 threads, other parity)
        if (t > 0 && tid < RPB) {
            float a = blv;
#pragma unroll
            for (int w = 0; w < 8; ++w) a += s_part[buf ^ 1][tid][w];
            s_log[tid * Nseq + (t - 1)] = a;
        }

        __syncthreads();   // ONE barrier: h(t+1), x planes, s_part ready
    }

    if (tid < RPB) {
        float a = blv;
#pragma unroll
        for (int w = 0; w < 8; ++w) a += s_part[(Nseq - 1) & 1][tid][w];
        s_log[tid * Nseq + (Nseq - 1)] = a;
    }
    __syncthreads();

    // ---- softmax over t: warp r handles row r ----
    {
        float v[16];
#pragma unroll
        for (int i = 0; i < 16; ++i)
            v[i] = s_log[wid * Nseq + i * 32 + lane];
        float m = v[0];
#pragma unroll
        for (int i = 1; i < 16; ++i) m = fmaxf(m, v[i]);
#pragma unroll
        for (int off = 16; off >= 1; off >>= 1)
            m = fmaxf(m, __shfl_xor_sync(0xffffffffu, m, off));

        float e[16], sum = 0.0f;
#pragma unroll
        for (int i = 0; i < 16; ++i) {
            e[i] = ex2a((v[i] - m) * 1.4426950408889634f);
            sum += e[i];
        }
#pragma unroll
        for (int off = 16; off >= 1; off >>= 1)
            sum += __shfl_xor_sync(0xffffffffu, sum, off);
        const float inv = 1.0f / sum;

        float* orow = out + (size_t)(b0 + wid) * Nseq;
#pragma unroll
        for (int i = 0; i < 16; ++i)
            orow[i * 32 + lane] = e[i] * inv;
    }
}

// ---------------------------------------------------------------------------
extern "C" void kernel_launch(void* const* d_in, const int* in_sizes, int n_in,
                              void* d_out, int out_size) {
    const float* x     = (const float*)d_in[0];
    const float* Wfc   = (const float*)d_in[1];
    const float* bfc   = (const float*)d_in[2];
    const float* Wih   = (const float*)d_in[3];
    const float* Whh   = (const float*)d_in[4];
    const float* bih   = (const float*)d_in[5];
    const float* bhh   = (const float*)d_in[6];
    const float* Wlast = (const float*)d_in[7];
    const float* blast = (const float*)d_in[8];
    float* out = (float*)d_out;

    prep_kernel<<<256, 32>>>(Wfc, bfc, Wih, Whh, bih, bhh);
    lstm_kernel<<<NBLK, 256>>>(x, Wlast, blast, out);
}

// round 15
// speedup vs baseline: 1.2239x; 1.2239x over previous
#include <cuda_runtime.h>
#include <cuda_fp16.h>
#include <cstdint>

// ---------------------------------------------------------------------------
// EnsembleHead fused. B=1024, N=512, D_IN=30, H=64, 4H=256.
// R13: R11 recurrence (single-pass tensor-pipe, fused input GEMM, one
// barrier/step) x TWO independent 256-thread groups per CTA, each with its
// own named barrier -> two recurrences interleave on each SM, hiding the
// step-latency critical path. 128 CTAs x 512 thr, 1/SM. Rows 4-7 of each
// group's M-tile are ghost rows (never read back).
// ---------------------------------------------------------------------------

typedef unsigned int uint32;

#define Bsz   1024
#define Nseq  512
#define DIN   30
#define RPB   8             // rows per CTA
#define RPG   4             // rows per group
#define NBLK  (Bsz / RPB)   // 128
#define KTOT  96            // 64 h + 32 x (30 used)
#define LDH   104           // halfs per SMEM row (h 0..63, x 64..95, pad)

__device__ __half g_wcomb_h[256 * KTOT];  // [n][k]: k<64 Whh, 64..93 Wc, 94/95 = 0
__device__ float  g_bc[256];

// ---------------- helpers ----------------
__device__ __forceinline__ float ex2a(float x) {
    float r; asm("ex2.approx.f32 %0, %1;" : "=f"(r) : "f"(x)); return r;
}
__device__ __forceinline__ float rcpa(float x) {
    float r; asm("rcp.approx.f32 %0, %1;" : "=f"(r) : "f"(x)); return r;
}
__device__ __forceinline__ float sigm(float x) {
    return rcpa(1.0f + ex2a(-1.4426950408889634f * x));
}
__device__ __forceinline__ float tanh_(float x) {
    return fmaf(2.0f, rcpa(1.0f + ex2a(-2.8853900817779268f * x)), -1.0f);
}
__device__ __forceinline__ void mma16816(float* c, uint32 a0, uint32 a1,
                                         uint32 a2, uint32 a3,
                                         uint32 b0, uint32 b1) {
    asm volatile(
        "mma.sync.aligned.m16n8k16.row.col.f32.f16.f16.f32 "
        "{%0,%1,%2,%3}, {%4,%5,%6,%7}, {%8,%9}, {%0,%1,%2,%3};"
        : "+f"(c[0]), "+f"(c[1]), "+f"(c[2]), "+f"(c[3])
        : "r"(a0), "r"(a1), "r"(a2), "r"(a3), "r"(b0), "r"(b1));
}

// ---------------------------------------------------------------------------
// prep: combined fp16 weight [n][96] = [Whh | Wih@Wfc | 0] and bias.
// grid=256 (n), block=32.
// ---------------------------------------------------------------------------
__global__ void prep_kernel(const float* __restrict__ Wfc,
                            const float* __restrict__ bfc,
                            const float* __restrict__ Wih,
                            const float* __restrict__ Whh,
                            const float* __restrict__ bih,
                            const float* __restrict__ bhh)
{
    const int j = blockIdx.x;
    const int lane = threadIdx.x;

    const float w1 = Wih[j * 64 + lane];
    const float w2 = Wih[j * 64 + lane + 32];
    float acc[DIN];
#pragma unroll
    for (int d = 0; d < DIN; ++d)
        acc[d] = w1 * Wfc[lane * DIN + d] + w2 * Wfc[(lane + 32) * DIN + d];
    float bs = w1 * bfc[lane] + w2 * bfc[lane + 32];

#pragma unroll
    for (int off = 16; off >= 1; off >>= 1) {
#pragma unroll
        for (int d = 0; d < DIN; ++d)
            acc[d] += __shfl_xor_sync(0xffffffffu, acc[d], off);
        bs += __shfl_xor_sync(0xffffffffu, bs, off);
    }

    g_wcomb_h[j * KTOT + 2 * lane]     = __float2half(Whh[j * 64 + 2 * lane]);
    g_wcomb_h[j * KTOT + 2 * lane + 1] = __float2half(Whh[j * 64 + 2 * lane + 1]);

    float a0 = 0.0f, a1 = 0.0f;
#pragma unroll
    for (int d = 0; d < DIN; ++d) {
        if (d == 2 * lane)     a0 = acc[d];
        if (d == 2 * lane + 1) a1 = acc[d];
    }
    if (lane < 16) {   // lane 15 writes zeros to cols 94,95
        g_wcomb_h[j * KTOT + 64 + 2 * lane]     = __float2half(a0);
        g_wcomb_h[j * KTOT + 64 + 2 * lane + 1] = __float2half(a1);
    }
    if (lane == 0) g_bc[j] = bs + bih[j] + bhh[j];
}

// ---------------------------------------------------------------------------
// lstm_kernel: 128 CTAs x 512 thr (2 groups x 8 warps), 1/SM.
// group grp handles rows b0..b0+3; thread (wid, gid, tig): row gid (<4 real),
// units u0 = wid*8 + tig*2, u0+1. Named barrier per group.
// ---------------------------------------------------------------------------
__global__ void __launch_bounds__(512, 1)
lstm_kernel(const float* __restrict__ X,
            const float* __restrict__ Wlast,
            const float* __restrict__ blast,
            float* __restrict__ out)
{
    __shared__ __align__(16) __half sh[2][2][8][LDH];  // [grp][buf][row][k]
    __shared__ float s_wl[64];
    __shared__ float s_part[2][2][RPG][8];             // [grp][parity][row][warp]
    __shared__ float s_log[2][RPG * Nseq];

    const int tid  = threadIdx.x;
    const int grp  = tid >> 8;
    const int ltid = tid & 255;
    const int lane = tid & 31;
    const int wid  = ltid >> 5;        // warp within group (0-7)
    const int gid  = lane >> 2;        // mma row (0-7; <4 real)
    const int tig  = lane & 3;
    const int b0   = blockIdx.x * RPB + grp * RPG;

    // zero h/x buffers (both groups), load Wlast
    for (int i = tid; i < (int)(sizeof(sh) / 4); i += 512) ((uint32*)sh)[i] = 0;
    if (tid < 64) s_wl[tid] = Wlast[tid];
    const float blv = blast[0];

    // B fragments: combined weight, n0 = gi*64 + wid*8 + gid
    uint32 bfr[4][6][2];
#pragma unroll
    for (int gi = 0; gi < 4; ++gi)
#pragma unroll
        for (int kt = 0; kt < 6; ++kt) {
            const int n0 = gi * 64 + wid * 8 + gid;
            const int k0 = kt * 16 + tig * 2;
            bfr[gi][kt][0] = *(const uint32*)(g_wcomb_h + n0 * KTOT + k0);
            bfr[gi][kt][1] = *(const uint32*)(g_wcomb_h + n0 * KTOT + k0 + 8);
        }
    float bia[4][2];
#pragma unroll
    for (int gi = 0; gi < 4; ++gi) {
        bia[gi][0] = g_bc[gi * 64 + wid * 8 + tig * 2];
        bia[gi][1] = g_bc[gi * 64 + wid * 8 + tig * 2 + 1];
    }

    // x staging role: ltid<120 owns (row prow, dim pd) of this group
    const bool px = ltid < RPG * DIN;
    const int prow = ltid / DIN;
    const int pd   = ltid - prow * DIN;
    const float* xp = X + ((size_t)(b0 + prow) * Nseq) * DIN + pd;

    __syncthreads();   // zero-fill complete (both groups)
    if (px) sh[grp][0][prow][64 + pd] = __float2half(xp[0]);
    __syncthreads();

    const float wl0 = s_wl[wid * 8 + tig * 2];
    const float wl1 = s_wl[wid * 8 + tig * 2 + 1];
    float cc0 = 0.0f, cc1 = 0.0f;
    const int barid = 1 + grp;

    for (int t = 0; t < Nseq; ++t) {
        const int buf = t & 1;

        // prefetch x(t+1)
        float xv = 0.0f;
        const bool pf = px && (t + 1 < Nseq);
        if (pf) xv = xp[(t + 1) * DIN];

        // A fragments (rows 8-15 zero -> a1=a3=0)
        uint32 afr0[6], afr2[6];
#pragma unroll
        for (int kt = 0; kt < 6; ++kt) {
            const int cb = kt * 16 + tig * 2;
            afr0[kt] = *(const uint32*)&sh[grp][buf][gid][cb];
            afr2[kt] = *(const uint32*)&sh[grp][buf][gid][cb + 8];
        }

        // tensor matvec: [h,x] @ Wcomb^T, warp's 4 n-tiles (one per gate)
        float cfr[4][4];
#pragma unroll
        for (int gi = 0; gi < 4; ++gi) {
            cfr[gi][0] = 0.f; cfr[gi][1] = 0.f; cfr[gi][2] = 0.f; cfr[gi][3] = 0.f;
#pragma unroll
            for (int kt = 0; kt < 6; ++kt)
                mma16816(cfr[gi], afr0[kt], 0u, afr2[kt], 0u,
                         bfr[gi][kt][0], bfr[gi][kt][1]);
        }

        // stage x(t+1) into the other buffer
        if (pf) sh[grp][buf ^ 1][prow][64 + pd] = __float2half(xv);

        // local activation + cell update (uniform; ghost rows harmless)
        float vi0 = cfr[0][0] + bia[0][0], vi1 = cfr[0][1] + bia[0][1];
        float vf0 = cfr[1][0] + bia[1][0], vf1 = cfr[1][1] + bia[1][1];
        float vg0 = cfr[2][0] + bia[2][0], vg1 = cfr[2][1] + bia[2][1];
        float vo0 = cfr[3][0] + bia[3][0], vo1 = cfr[3][1] + bia[3][1];

        float i0 = sigm(vi0), f0 = sigm(vf0), g0 = tanh_(vg0), o0 = sigm(vo0);
        float i1 = sigm(vi1), f1 = sigm(vf1), g1 = tanh_(vg1), o1 = sigm(vo1);
        cc0 = fmaf(f0, cc0, i0 * g0);
        cc1 = fmaf(f1, cc1, i1 * g1);
        float hv0 = o0 * tanh_(cc0);
        float hv1 = o1 * tanh_(cc1);

        // h(t+1) -> other buffer (units adjacent: one half2 store)
        *(__half2*)&sh[grp][buf ^ 1][gid][wid * 8 + tig * 2] =
            __floats2half2_rn(hv0, hv1);

        // logit partial for real rows, parity-buffered
        float p = hv0 * wl0 + hv1 * wl1;
        p += __shfl_down_sync(0xffffffffu, p, 1, 4);
        p += __shfl_down_sync(0xffffffffu, p, 2, 4);
        if (tig == 0 && gid < RPG) s_part[grp][buf][gid][wid] = p;

        // combine previous step's logit partials (4 threads/group)
        if (t > 0 && ltid < RPG) {
            float a = blv;
#pragma unroll
            for (int w = 0; w < 8; ++w) a += s_part[grp][buf ^ 1][ltid][w];
            s_log[grp][ltid * Nseq + (t - 1)] = a;
        }

        // ONE group-local barrier: h(t+1), x(t+1), s_part ready
        asm volatile("bar.sync %0, %1;" :: "r"(barid), "r"(256) : "memory");
    }

    if (ltid < RPG) {
        float a = blv;
#pragma unroll
        for (int w = 0; w < 8; ++w) a += s_part[grp][(Nseq - 1) & 1][ltid][w];
        s_log[grp][ltid * Nseq + (Nseq - 1)] = a;
    }
    asm volatile("bar.sync %0, %1;" :: "r"(barid), "r"(256) : "memory");

    // ---- softmax over t: warp wid (<4) handles row b0+wid of its group ----
    if (wid < RPG) {
        float v[16];
#pragma unroll
        for (int i = 0; i < 16; ++i)
            v[i] = s_log[grp][wid * Nseq + i * 32 + lane];
        float m = v[0];
#pragma unroll
        for (int i = 1; i < 16; ++i) m = fmaxf(m, v[i]);
#pragma unroll
        for (int off = 16; off >= 1; off >>= 1)
            m = fmaxf(m, __shfl_xor_sync(0xffffffffu, m, off));

        float e[16], sum = 0.0f;
#pragma unroll
        for (int i = 0; i < 16; ++i) {
            e[i] = ex2a((v[i] - m) * 1.4426950408889634f);
            sum += e[i];
        }
#pragma unroll
        for (int off = 16; off >= 1; off >>= 1)
            sum += __shfl_xor_sync(0xffffffffu, sum, off);
        const float inv = 1.0f / sum;

        float* orow = out + (size_t)(b0 + wid) * Nseq;
#pragma unroll
        for (int i = 0; i < 16; ++i)
            orow[i * 32 + lane] = e[i] * inv;
    }
}

// ---------------------------------------------------------------------------
extern "C" void kernel_launch(void* const* d_in, const int* in_sizes, int n_in,
                              void* d_out, int out_size) {
    const float* x     = (const float*)d_in[0];
    const float* Wfc   = (const float*)d_in[1];
    const float* bfc   = (const float*)d_in[2];
    const float* Wih   = (const float*)d_in[3];
    const float* Whh   = (const float*)d_in[4];
    const float* bih   = (const float*)d_in[5];
    const float* bhh   = (const float*)d_in[6];
    const float* Wlast = (const float*)d_in[7];
    const float* blast = (const float*)d_in[8];
    float* out = (float*)d_out;

    prep_kernel<<<256, 32>>>(Wfc, bfc, Wih, Whh, bih, bhh);
    lstm_kernel<<<NBLK, 512>>>(x, Wlast, blast, out);
}

// round 16
// speedup vs baseline: 2.1280x; 1.7388x over previous
#include <cuda_runtime.h>
#include <cuda_fp16.h>
#include <cstdint>

// ---------------------------------------------------------------------------
// EnsembleHead fused. B=1024, N=512, D_IN=30, H=64, 4H=256.
// R15: R11 skeleton (single-pass tensor-pipe recurrence, fused input GEMM,
// one barrier/step, 128 CTAs x 256 thr) + MUFU.TANH activations:
// tanh.approx.f32 (1 MUFU) and sigmoid via 0.5*tanh(x/2)+0.5 -> per-thread
// MUFU count halves (20 -> 10), cutting ~320 cyc/SMSP off the step.
// ---------------------------------------------------------------------------

typedef unsigned int uint32;

#define Bsz   1024
#define Nseq  512
#define DIN   30
#define RPB   8
#define NBLK  (Bsz / RPB)   // 128
#define KTOT  96            // 64 h + 32 x (30 used)
#define LDH   104           // halfs per SMEM row (h 0..63, x 64..95, pad)

__device__ __half g_wcomb_h[256 * KTOT];  // [n][k]: k<64 Whh, 64..93 Wc, 94/95 = 0
__device__ float  g_bc[256];

// ---------------- helpers ----------------
__device__ __forceinline__ float ex2a(float x) {
    float r; asm("ex2.approx.f32 %0, %1;" : "=f"(r) : "f"(x)); return r;
}
__device__ __forceinline__ float tanha(float x) {
    float r; asm("tanh.approx.f32 %0, %1;" : "=f"(r) : "f"(x)); return r;
}
__device__ __forceinline__ float sigm(float x) {
    return fmaf(0.5f, tanha(0.5f * x), 0.5f);   // 1 MUFU + 1 FMA
}
__device__ __forceinline__ void mma16816(float* c, uint32 a0, uint32 a1,
                                         uint32 a2, uint32 a3,
                                         uint32 b0, uint32 b1) {
    asm volatile(
        "mma.sync.aligned.m16n8k16.row.col.f32.f16.f16.f32 "
        "{%0,%1,%2,%3}, {%4,%5,%6,%7}, {%8,%9}, {%0,%1,%2,%3};"
        : "+f"(c[0]), "+f"(c[1]), "+f"(c[2]), "+f"(c[3])
        : "r"(a0), "r"(a1), "r"(a2), "r"(a3), "r"(b0), "r"(b1));
}

// ---------------------------------------------------------------------------
// prep: combined fp16 weight [n][96] = [Whh | Wih@Wfc | 0] and bias.
// grid=256 (n), block=32.
// ---------------------------------------------------------------------------
__global__ void prep_kernel(const float* __restrict__ Wfc,
                            const float* __restrict__ bfc,
                            const float* __restrict__ Wih,
                            const float* __restrict__ Whh,
                            const float* __restrict__ bih,
                            const float* __restrict__ bhh)
{
    const int j = blockIdx.x;
    const int lane = threadIdx.x;

    const float w1 = Wih[j * 64 + lane];
    const float w2 = Wih[j * 64 + lane + 32];
    float acc[DIN];
#pragma unroll
    for (int d = 0; d < DIN; ++d)
        acc[d] = w1 * Wfc[lane * DIN + d] + w2 * Wfc[(lane + 32) * DIN + d];
    float bs = w1 * bfc[lane] + w2 * bfc[lane + 32];

#pragma unroll
    for (int off = 16; off >= 1; off >>= 1) {
#pragma unroll
        for (int d = 0; d < DIN; ++d)
            acc[d] += __shfl_xor_sync(0xffffffffu, acc[d], off);
        bs += __shfl_xor_sync(0xffffffffu, bs, off);
    }

    g_wcomb_h[j * KTOT + 2 * lane]     = __float2half(Whh[j * 64 + 2 * lane]);
    g_wcomb_h[j * KTOT + 2 * lane + 1] = __float2half(Whh[j * 64 + 2 * lane + 1]);

    float a0 = 0.0f, a1 = 0.0f;
#pragma unroll
    for (int d = 0; d < DIN; ++d) {
        if (d == 2 * lane)     a0 = acc[d];
        if (d == 2 * lane + 1) a1 = acc[d];
    }
    if (lane < 16) {   // lane 15 writes zeros to cols 94,95
        g_wcomb_h[j * KTOT + 64 + 2 * lane]     = __float2half(a0);
        g_wcomb_h[j * KTOT + 64 + 2 * lane + 1] = __float2half(a1);
    }
    if (lane == 0) g_bc[j] = bs + bih[j] + bhh[j];
}

// ---------------------------------------------------------------------------
// lstm_kernel: 128 CTAs x 256 thr (8 warps), 1/SM.
// thread (wid, gid=lane>>2, tig=lane&3): row gid, units u0=wid*8+tig*2, u0+1.
// ---------------------------------------------------------------------------
__global__ void __launch_bounds__(256, 1)
lstm_kernel(const float* __restrict__ X,
            const float* __restrict__ Wlast,
            const float* __restrict__ blast,
            float* __restrict__ out)
{
    __shared__ __align__(16) __half sh[2][RPB][LDH];  // [buf][row][k]: h 0..63, x 64..95
    __shared__ float s_wl[64];
    __shared__ float s_part[2][RPB][8];               // [parity][row][warp]
    __shared__ float s_log[RPB * Nseq];

    const int tid  = threadIdx.x;
    const int lane = tid & 31;
    const int wid  = tid >> 5;
    const int b0   = blockIdx.x * RPB;
    const int gid  = lane >> 2;
    const int tig  = lane & 3;

    // zero both SMEM buffers (h and x pad regions), load Wlast
    for (int i = tid; i < (int)(2 * RPB * LDH / 2); i += 256) ((uint32*)sh)[i] = 0;
    if (tid < 64) s_wl[tid] = Wlast[tid];
    const float blv = blast[0];

    // B fragments: combined weight, n0 = gi*64 + wid*8 + gid
    uint32 bfr[4][6][2];
#pragma unroll
    for (int gi = 0; gi < 4; ++gi)
#pragma unroll
        for (int kt = 0; kt < 6; ++kt) {
            const int n0 = gi * 64 + wid * 8 + gid;
            const int k0 = kt * 16 + tig * 2;
            bfr[gi][kt][0] = *(const uint32*)(g_wcomb_h + n0 * KTOT + k0);
            bfr[gi][kt][1] = *(const uint32*)(g_wcomb_h + n0 * KTOT + k0 + 8);
        }
    // biases for this thread's 2 units x 4 gates
    float bia[4][2];
#pragma unroll
    for (int gi = 0; gi < 4; ++gi) {
        bia[gi][0] = g_bc[gi * 64 + wid * 8 + tig * 2];
        bia[gi][1] = g_bc[gi * 64 + wid * 8 + tig * 2 + 1];
    }

    // x prefetch role: tid<240 owns (row, d)
    const bool px = tid < RPB * DIN;
    const int prow = tid / DIN;
    const int pd   = tid - prow * DIN;
    const float* xp = X + ((size_t)(b0 + prow) * Nseq) * DIN + pd;

    __syncthreads();   // zero-fill complete before x(0) staging
    if (px) sh[0][prow][64 + pd] = __float2half(xp[0]);
    __syncthreads();

    const float wl0 = s_wl[wid * 8 + tig * 2];
    const float wl1 = s_wl[wid * 8 + tig * 2 + 1];
    float cc0 = 0.0f, cc1 = 0.0f;

    for (int t = 0; t < Nseq; ++t) {
        const int buf = t & 1;

        // prefetch x(t+1)
        float xv = 0.0f;
        const bool pf = px && (t + 1 < Nseq);
        if (pf) xv = xp[(t + 1) * DIN];

        // A fragments (rows 8-15 are zero -> a1=a3=0)
        uint32 afr0[6], afr2[6];
#pragma unroll
        for (int kt = 0; kt < 6; ++kt) {
            const int cb = kt * 16 + tig * 2;
            afr0[kt] = *(const uint32*)&sh[buf][gid][cb];
            afr2[kt] = *(const uint32*)&sh[buf][gid][cb + 8];
        }

        // tensor matvec: [h,x] @ Wcomb^T, warp's 4 n-tiles (one per gate)
        float cfr[4][4];
#pragma unroll
        for (int gi = 0; gi < 4; ++gi) {
            cfr[gi][0] = 0.f; cfr[gi][1] = 0.f; cfr[gi][2] = 0.f; cfr[gi][3] = 0.f;
#pragma unroll
            for (int kt = 0; kt < 6; ++kt)
                mma16816(cfr[gi], afr0[kt], 0u, afr2[kt], 0u,
                         bfr[gi][kt][0], bfr[gi][kt][1]);
        }

        // stage x(t+1) into other buffer
        if (pf) sh[buf ^ 1][prow][64 + pd] = __float2half(xv);

        // local activation + cell update (all four gates in-register)
        float vi0 = cfr[0][0] + bia[0][0], vi1 = cfr[0][1] + bia[0][1];
        float vf0 = cfr[1][0] + bia[1][0], vf1 = cfr[1][1] + bia[1][1];
        float vg0 = cfr[2][0] + bia[2][0], vg1 = cfr[2][1] + bia[2][1];
        float vo0 = cfr[3][0] + bia[3][0], vo1 = cfr[3][1] + bia[3][1];

        float i0 = sigm(vi0), f0 = sigm(vf0), g0 = tanha(vg0), o0 = sigm(vo0);
        float i1 = sigm(vi1), f1 = sigm(vf1), g1 = tanha(vg1), o1 = sigm(vo1);
        cc0 = fmaf(f0, cc0, i0 * g0);
        cc1 = fmaf(f1, cc1, i1 * g1);
        float hv0 = o0 * tanha(cc0);
        float hv1 = o1 * tanha(cc1);

        // h(t+1) -> other buffer (units adjacent: one half2 store)
        *(__half2*)&sh[buf ^ 1][gid][wid * 8 + tig * 2] =
            __floats2half2_rn(hv0, hv1);

        // logit partial for row gid (this warp's 8 units), parity-buffered
        float p = hv0 * wl0 + hv1 * wl1;
        p += __shfl_down_sync(0xffffffffu, p, 1, 4);
        p += __shfl_down_sync(0xffffffffu, p, 2, 4);
        if (tig == 0) s_part[buf][gid][wid] = p;

        // combine previous step's logit partials (8 threads, other parity)
        if (t > 0 && tid < RPB) {
            float a = blv;
#pragma unroll
            for (int w = 0; w < 8; ++w) a += s_part[buf ^ 1][tid][w];
            s_log[tid * Nseq + (t - 1)] = a;
        }

        __syncthreads();   // ONE barrier: h(t+1), x(t+1), s_part ready
    }

    if (tid < RPB) {
        float a = blv;
#pragma unroll
        for (int w = 0; w < 8; ++w) a += s_part[(Nseq - 1) & 1][tid][w];
        s_log[tid * Nseq + (Nseq - 1)] = a;
    }
    __syncthreads();

    // ---- softmax over t: warp r handles row r ----
    {
        float v[16];
#pragma unroll
        for (int i = 0; i < 16; ++i)
            v[i] = s_log[wid * Nseq + i * 32 + lane];
        float m = v[0];
#pragma unroll
        for (int i = 1; i < 16; ++i) m = fmaxf(m, v[i]);
#pragma unroll
        for (int off = 16; off >= 1; off >>= 1)
            m = fmaxf(m, __shfl_xor_sync(0xffffffffu, m, off));

        float e[16], sum = 0.0f;
#pragma unroll
        for (int i = 0; i < 16; ++i) {
            e[i] = ex2a((v[i] - m) * 1.4426950408889634f);
            sum += e[i];
        }
#pragma unroll
        for (int off = 16; off >= 1; off >>= 1)
            sum += __shfl_xor_sync(0xffffffffu, sum, off);
        const float inv = 1.0f / sum;

        float* orow = out + (size_t)(b0 + wid) * Nseq;
#pragma unroll
        for (int i = 0; i < 16; ++i)
            orow[i * 32 + lane] = e[i] * inv;
    }
}

// ---------------------------------------------------------------------------
extern "C" void kernel_launch(void* const* d_in, const int* in_sizes, int n_in,
                              void* d_out, int out_size) {
    const float* x     = (const float*)d_in[0];
    const float* Wfc   = (const float*)d_in[1];
    const float* bfc   = (const float*)d_in[2];
    const float* Wih   = (const float*)d_in[3];
    const float* Whh   = (const float*)d_in[4];
    const float* bih   = (const float*)d_in[5];
    const float* bhh   = (const float*)d_in[6];
    const float* Wlast = (const float*)d_in[7];
    const float* blast = (const float*)d_in[8];
    float* out = (float*)d_out;

    prep_kernel<<<256, 32>>>(Wfc, bfc, Wih, Whh, bih, bhh);
    lstm_kernel<<<NBLK, 256>>>(x, Wlast, blast, out);
}